// round 1
// baseline (speedup 1.0000x reference)
#include <cuda_runtime.h>
#include <math.h>

#define BB 2
#define CC 256
#define HH 200
#define WW 304
#define HW (HH * WW)
#define HWC (HH * WW * CC)
#define OUTH 7
#define OUTW 7
#define NBINS (OUTH * OUTW)
#define SRR 2
#define NSAMP (OUTH * SRR * OUTW * SRR)   /* 196 */
#define SCALE 0.25f

// NHWC scratch: (B, H, W, C) float32 — 124.5 MB static device array (allowed).
__device__ float g_nhwc[(size_t)BB * HW * CC];

// ---------------------------------------------------------------------------
// Kernel 1: NCHW -> NHWC transpose. Per batch, transpose (C=256, HW=60800).
// Classic 32x32 smem tile, 32x8 threads, 4 rows per thread.
// ---------------------------------------------------------------------------
__global__ __launch_bounds__(256) void nchw_to_nhwc(const float* __restrict__ in) {
    __shared__ float tile[32][33];
    const int b   = blockIdx.z;
    const int hw0 = blockIdx.x * 32;
    const int c0  = blockIdx.y * 32;   // C=256 divisible by 32, no guard needed
    const int tx  = threadIdx.x;       // 0..31
    const int ty  = threadIdx.y;       // 0..7

    const float* src = in + (size_t)b * CC * HW;
#pragma unroll
    for (int i = 0; i < 32; i += 8) {
        int c  = c0 + ty + i;
        int hw = hw0 + tx;
        float v = 0.0f;
        if (hw < HW) v = src[(size_t)c * HW + hw];
        tile[ty + i][tx] = v;
    }
    __syncthreads();

    float* dst = g_nhwc + (size_t)b * HW * CC;
#pragma unroll
    for (int i = 0; i < 32; i += 8) {
        int hw = hw0 + ty + i;
        int c  = c0 + tx;
        if (hw < HW) dst[(size_t)hw * CC + c] = tile[tx][ty + i];
    }
}

// ---------------------------------------------------------------------------
// Kernel 2: rotated ROI align. One block per ROI, 256 threads = channels.
// Threads 0..195 precompute the 196 sample corner offsets + weights.
// Each thread accumulates 49 bins (4 samples x 4 corners each), results
// staged in padded smem (stride 257 -> conflict-free in both phases), then
// written out coalesced in two chunks (25 + 24 bins) to keep smem < 48 KB.
// ---------------------------------------------------------------------------
#define CHUNK0 25
#define CHUNK1 24
#define SPAD 257

struct AlignSmem {
    int4   o[NSAMP];         // 4 corner offsets (already *CC)
    float4 w[NSAMP];         // 4 bilinear weights (zeroed if sample empty)
    float  stage[CHUNK0 * SPAD];
    int    base_b;
};

template <int B0, int CNT>
__device__ __forceinline__ void flush_chunk(AlignSmem& sm, float* __restrict__ o, int tid) {
    // out layout per ROI: c * 49 + bin (contiguous 12544-float region)
    for (int k = tid; k < CC * CNT; k += 256) {
        int c   = k / CNT;          // const divisor -> mul
        int bin = k % CNT;
        o[c * NBINS + B0 + bin] = sm.stage[bin * SPAD + c];
    }
}

__global__ __launch_bounds__(256) void roi_align_rotated(
    const float* __restrict__ rois, float* __restrict__ out) {
    __shared__ AlignSmem sm;
    const int n   = blockIdx.x;
    const int tid = threadIdx.x;
    const float* r = rois + (size_t)n * 6;

    if (tid < NSAMP) {
        float cw = r[1] * SCALE - 0.5f;
        float ch = r[2] * SCALE - 0.5f;
        float rw = r[3] * SCALE;
        float rh = r[4] * SCALE;
        float theta = r[5] * (float)(M_PI / 180.0);
        float st, ct;
        sincosf(theta, &st, &ct);

        int i = tid / 14;   // y sample index 0..13
        int j = tid % 14;   // x sample index 0..13
        float bin_h = rh * (1.0f / OUTH);
        float bin_w = rw * (1.0f / OUTW);
        float ty = (i + 0.5f) * (1.0f / SRR);
        float tx = (j + 0.5f) * (1.0f / SRR);
        float yy = -rh * 0.5f + ty * bin_h;
        float xx = -rw * 0.5f + tx * bin_w;
        float y = yy * ct - xx * st + ch;
        float x = yy * st + xx * ct + cw;

        bool empty = (y < -1.0f) | (y > (float)HH) | (x < -1.0f) | (x > (float)WW);
        y = fmaxf(y, 0.0f);
        x = fmaxf(x, 0.0f);
        int yl = min((int)floorf(y), HH - 1);
        int xl = min((int)floorf(x), WW - 1);
        int yh = min(yl + 1, HH - 1);
        int xh = min(xl + 1, WW - 1);
        float ly = fminf(y - (float)yl, 1.0f);
        float lx = fminf(x - (float)xl, 1.0f);
        float hy = 1.0f - ly, hx = 1.0f - lx;
        float w1 = hy * hx, w2 = hy * lx, w3 = ly * hx, w4 = ly * lx;
        if (empty) { w1 = w2 = w3 = w4 = 0.0f; }

        sm.o[tid] = make_int4((yl * WW + xl) * CC, (yl * WW + xh) * CC,
                              (yh * WW + xl) * CC, (yh * WW + xh) * CC);
        sm.w[tid] = make_float4(w1, w2, w3, w4);
    }
    if (tid == 0) sm.base_b = (int)r[0];
    __syncthreads();

    const float* __restrict__ f = g_nhwc + (size_t)sm.base_b * HWC + tid; // channel = tid
    float* __restrict__ o_roi = out + (size_t)n * (CC * NBINS);

    // --- chunk 0: bins [0, 25) ---
#pragma unroll 1
    for (int bin = 0; bin < CHUNK0; bin++) {
        int ph = bin / OUTW, pw = bin % OUTW;
        float acc = 0.0f;
#pragma unroll
        for (int iy = 0; iy < SRR; iy++) {
#pragma unroll
            for (int ix = 0; ix < SRR; ix++) {
                int s = (ph * SRR + iy) * (OUTW * SRR) + (pw * SRR + ix);
                int4   o = sm.o[s];
                float4 w = sm.w[s];
                acc += w.x * __ldg(f + o.x);
                acc += w.y * __ldg(f + o.y);
                acc += w.z * __ldg(f + o.z);
                acc += w.w * __ldg(f + o.w);
            }
        }
        sm.stage[bin * SPAD + tid] = acc * 0.25f;
    }
    __syncthreads();
    flush_chunk<0, CHUNK0>(sm, o_roi, tid);
    __syncthreads();

    // --- chunk 1: bins [25, 49) ---
#pragma unroll 1
    for (int bin = CHUNK0; bin < NBINS; bin++) {
        int ph = bin / OUTW, pw = bin % OUTW;
        float acc = 0.0f;
#pragma unroll
        for (int iy = 0; iy < SRR; iy++) {
#pragma unroll
            for (int ix = 0; ix < SRR; ix++) {
                int s = (ph * SRR + iy) * (OUTW * SRR) + (pw * SRR + ix);
                int4   o = sm.o[s];
                float4 w = sm.w[s];
                acc += w.x * __ldg(f + o.x);
                acc += w.y * __ldg(f + o.y);
                acc += w.z * __ldg(f + o.z);
                acc += w.w * __ldg(f + o.w);
            }
        }
        sm.stage[(bin - CHUNK0) * SPAD + tid] = acc * 0.25f;
    }
    __syncthreads();
    flush_chunk<CHUNK0, CHUNK1>(sm, o_roi, tid);
}

// ---------------------------------------------------------------------------
extern "C" void kernel_launch(void* const* d_in, const int* in_sizes, int n_in,
                              void* d_out, int out_size) {
    const float* feats = (const float*)d_in[0];  // (2,256,200,304) f32
    const float* rois  = (const float*)d_in[1];  // (N,6) f32
    float* out = (float*)d_out;                  // (N,256,7,7) f32
    int n_rois = in_sizes[1] / 6;

    dim3 tgrid((HW + 31) / 32, CC / 32, BB);
    nchw_to_nhwc<<<tgrid, dim3(32, 8)>>>(feats);

    roi_align_rotated<<<n_rois, 256>>>(rois, out);
}

// round 2
// speedup vs baseline: 1.0528x; 1.0528x over previous
#include <cuda_runtime.h>
#include <math.h>

#define BB 2
#define CC 256
#define HH 200
#define WW 304
#define HW (HH * WW)
#define HWC (HH * WW * CC)
#define OUTH 7
#define OUTW 7
#define NBINS (OUTH * OUTW)
#define SRR 2
#define NSAMP (OUTH * SRR * OUTW * SRR)   /* 196 */
#define SCALE 0.25f

// NHWC scratch: (B, H, W, C) float32 — 124.5 MB static device array (allowed).
__device__ float g_nhwc[(size_t)BB * HW * CC];

// ---------------------------------------------------------------------------
// Kernel 1: NCHW -> NHWC transpose. Per batch, transpose (C=256, HW=60800).
// Classic 32x32 smem tile, 32x8 threads, 4 rows per thread.
// ---------------------------------------------------------------------------
__global__ __launch_bounds__(256) void nchw_to_nhwc(const float* __restrict__ in) {
    __shared__ float tile[32][33];
    const int b   = blockIdx.z;
    const int hw0 = blockIdx.x * 32;
    const int c0  = blockIdx.y * 32;
    const int tx  = threadIdx.x;       // 0..31
    const int ty  = threadIdx.y;       // 0..7

    const float* src = in + (size_t)b * CC * HW;
#pragma unroll
    for (int i = 0; i < 32; i += 8) {
        int c  = c0 + ty + i;
        int hw = hw0 + tx;
        float v = 0.0f;
        if (hw < HW) v = src[(size_t)c * HW + hw];
        tile[ty + i][tx] = v;
    }
    __syncthreads();

    float* dst = g_nhwc + (size_t)b * HW * CC;
#pragma unroll
    for (int i = 0; i < 32; i += 8) {
        int hw = hw0 + ty + i;
        int c  = c0 + tx;
        if (hw < HW) dst[(size_t)hw * CC + c] = tile[tx][ty + i];
    }
}

// ---------------------------------------------------------------------------
// Kernel 2: rotated ROI align. One block per ROI, 128 threads; each thread
// owns 2 adjacent channels (float2 gathers -> 256B/warp, fully coalesced).
// Low resource footprint: ~13.6 KB smem, <=42 regs target => 12 blocks/SM
// => 1776 concurrent blocks => all 1000 ROIs in ONE wave (R1 ran 2 waves).
// Results staged in smem 7 bins at a time (float index bin*260 + c), then
// flushed coalesced to the c*49+bin output layout.
// ---------------------------------------------------------------------------
#define TPB 128
#define CHB 7            /* bins per stage chunk */
#define SPADF 260        /* floats per staged bin row (2*130) */

struct AlignSmem {
    int4   o[NSAMP];             // 4 corner offsets in float2 units (pix*128)
    float4 w[NSAMP];             // 4 bilinear weights (zeroed if empty)
    float2 stage[CHB * (SPADF / 2)];
    int    base_b;
};

__global__ __launch_bounds__(TPB) void roi_align_rotated(
    const float* __restrict__ rois, float* __restrict__ out) {
    __shared__ AlignSmem sm;
    const int n   = blockIdx.x;
    const int tid = threadIdx.x;
    const float* r = rois + (size_t)n * 6;

    // precompute the 196 samples with 128 threads (tid and tid+128)
#pragma unroll
    for (int s = tid; s < NSAMP; s += TPB) {
        float cw = r[1] * SCALE - 0.5f;
        float ch = r[2] * SCALE - 0.5f;
        float rw = r[3] * SCALE;
        float rh = r[4] * SCALE;
        float theta = r[5] * (float)(M_PI / 180.0);
        float st, ct;
        sincosf(theta, &st, &ct);

        int i = s / (OUTW * SRR);   // y sample index 0..13
        int j = s % (OUTW * SRR);   // x sample index 0..13
        float bin_h = rh * (1.0f / OUTH);
        float bin_w = rw * (1.0f / OUTW);
        float ty = (i + 0.5f) * (1.0f / SRR);
        float tx = (j + 0.5f) * (1.0f / SRR);
        float yy = -rh * 0.5f + ty * bin_h;
        float xx = -rw * 0.5f + tx * bin_w;
        float y = yy * ct - xx * st + ch;
        float x = yy * st + xx * ct + cw;

        bool empty = (y < -1.0f) | (y > (float)HH) | (x < -1.0f) | (x > (float)WW);
        y = fmaxf(y, 0.0f);
        x = fmaxf(x, 0.0f);
        int yl = min((int)floorf(y), HH - 1);
        int xl = min((int)floorf(x), WW - 1);
        int yh = min(yl + 1, HH - 1);
        int xh = min(xl + 1, WW - 1);
        float ly = fminf(y - (float)yl, 1.0f);
        float lx = fminf(x - (float)xl, 1.0f);
        float hy = 1.0f - ly, hx = 1.0f - lx;
        float w1 = hy * hx, w2 = hy * lx, w3 = ly * hx, w4 = ly * lx;
        if (empty) { w1 = w2 = w3 = w4 = 0.0f; }

        // offsets in float2 units: pixel * CC / 2 = pixel * 128
        sm.o[s] = make_int4((yl * WW + xl) * (CC / 2), (yl * WW + xh) * (CC / 2),
                            (yh * WW + xl) * (CC / 2), (yh * WW + xh) * (CC / 2));
        sm.w[s] = make_float4(w1, w2, w3, w4);
    }
    if (tid == 0) sm.base_b = (int)r[0];
    __syncthreads();

    // thread owns channels {2*tid, 2*tid+1}
    const float2* __restrict__ f =
        (const float2*)(g_nhwc + (size_t)sm.base_b * HWC) + tid;
    float* __restrict__ o_roi = out + (size_t)n * (CC * NBINS);
    float* __restrict__ stagef = (float*)sm.stage;

    for (int b0 = 0; b0 < NBINS; b0 += CHB) {
#pragma unroll 1
        for (int bi = 0; bi < CHB; bi++) {
            int bin = b0 + bi;
            int ph = bin / OUTW, pw = bin % OUTW;
            float ax = 0.0f, ay = 0.0f;
#pragma unroll
            for (int iy = 0; iy < SRR; iy++) {
#pragma unroll
                for (int ix = 0; ix < SRR; ix++) {
                    int s = (ph * SRR + iy) * (OUTW * SRR) + (pw * SRR + ix);
                    int4   o = sm.o[s];
                    float4 w = sm.w[s];
                    float2 v1 = __ldg(f + o.x);
                    float2 v2 = __ldg(f + o.y);
                    float2 v3 = __ldg(f + o.z);
                    float2 v4 = __ldg(f + o.w);
                    ax += w.x * v1.x; ay += w.x * v1.y;
                    ax += w.y * v2.x; ay += w.y * v2.y;
                    ax += w.z * v3.x; ay += w.z * v3.y;
                    ax += w.w * v4.x; ay += w.w * v4.y;
                }
            }
            // float layout: channel c lives at stagef[bi*SPADF + c]
            sm.stage[bi * (SPADF / 2) + tid] = make_float2(ax * 0.25f, ay * 0.25f);
        }
        __syncthreads();
        // coalesced flush: consecutive k -> consecutive output addresses
        for (int k = tid; k < CC * CHB; k += TPB) {
            int c   = k / CHB;
            int bin = k % CHB;
            o_roi[c * NBINS + b0 + bin] = stagef[bin * SPADF + c];
        }
        __syncthreads();
    }
}

// ---------------------------------------------------------------------------
extern "C" void kernel_launch(void* const* d_in, const int* in_sizes, int n_in,
                              void* d_out, int out_size) {
    const float* feats = (const float*)d_in[0];  // (2,256,200,304) f32
    const float* rois  = (const float*)d_in[1];  // (N,6) f32
    float* out = (float*)d_out;                  // (N,256,7,7) f32
    int n_rois = in_sizes[1] / 6;

    dim3 tgrid((HW + 31) / 32, CC / 32, BB);
    nchw_to_nhwc<<<tgrid, dim3(32, 8)>>>(feats);

    roi_align_rotated<<<n_rois, TPB>>>(rois, out);
}

// round 3
// speedup vs baseline: 1.6323x; 1.5505x over previous
#include <cuda_runtime.h>
#include <cuda_fp16.h>
#include <math.h>

#define BB 2
#define CC 256
#define HH 200
#define WW 304
#define HW (HH * WW)
#define HWC (HH * WW * CC)
#define OUTH 7
#define OUTW 7
#define NBINS (OUTH * OUTW)
#define SRR 2
#define NSAMP (OUTH * SRR * OUTW * SRR)   /* 196 */
#define SCALE 0.25f

// NHWC fp16 scratch: (B, H, W, C) — 62.3 MB static device array (fits in L2).
__device__ __half g_nhwcH[(size_t)BB * HW * CC];

// ---------------------------------------------------------------------------
// Kernel 1: NCHW f32 -> NHWC fp16. Tile 64 channels x 32 hw positions.
// Write phase packs channel pairs into half2 -> 128B/warp stores.
// ---------------------------------------------------------------------------
__global__ __launch_bounds__(256) void nchw_to_nhwc_h(const float* __restrict__ in) {
    __shared__ float tile[64][33];
    const int b   = blockIdx.z;
    const int hw0 = blockIdx.x * 32;
    const int c0  = blockIdx.y * 64;
    const int tx  = threadIdx.x;       // 0..31
    const int ty  = threadIdx.y;       // 0..7

    const float* src = in + (size_t)b * CC * HW;
#pragma unroll
    for (int i = 0; i < 64; i += 8) {
        int c  = c0 + ty + i;
        int hw = hw0 + tx;
        float v = 0.0f;
        if (hw < HW) v = src[(size_t)c * HW + hw];
        tile[ty + i][tx] = v;
    }
    __syncthreads();

    __half2* dst = (__half2*)(g_nhwcH + (size_t)b * HW * CC);
#pragma unroll
    for (int i = 0; i < 32; i += 8) {
        int hw = hw0 + ty + i;
        if (hw < HW) {
            float va = tile[2 * tx][ty + i];
            float vb = tile[2 * tx + 1][ty + i];
            dst[((size_t)hw * CC + c0) / 2 + tx] = __floats2half2_rn(va, vb);
        }
    }
}

// ---------------------------------------------------------------------------
// Kernel 2: rotated ROI align on fp16 NHWC. Grid (n_rois, 2): blockIdx.y
// splits the 49 bins 28/21 (both multiples of the 7-bin stage chunk).
// 128 threads, thread owns channels {2t, 2t+1} via half2 gathers (512B/warp,
// fully coalesced), fp32 accumulation. ~13.7KB smem => 14+ blocks/SM.
// ---------------------------------------------------------------------------
#define TPB 128
#define CHB 7            /* bins per stage chunk */
#define SPADF 260        /* floats per staged bin row */

struct AlignSmem {
    int4   o[NSAMP];             // 4 corner offsets in half2 units (pix*128)
    float4 w[NSAMP];             // 4 bilinear weights (zeroed if empty)
    float2 stage[CHB * (SPADF / 2)];
    int    base_b;
};

__global__ __launch_bounds__(TPB) void roi_align_rotated(
    const float* __restrict__ rois, float* __restrict__ out) {
    __shared__ AlignSmem sm;
    const int n   = blockIdx.x;
    const int tid = threadIdx.x;
    const float* r = rois + (size_t)n * 6;

#pragma unroll
    for (int s = tid; s < NSAMP; s += TPB) {
        float cw = r[1] * SCALE - 0.5f;
        float ch = r[2] * SCALE - 0.5f;
        float rw = r[3] * SCALE;
        float rh = r[4] * SCALE;
        float theta = r[5] * (float)(M_PI / 180.0);
        float st, ct;
        sincosf(theta, &st, &ct);

        int i = s / (OUTW * SRR);   // y sample index 0..13
        int j = s % (OUTW * SRR);   // x sample index 0..13
        float bin_h = rh * (1.0f / OUTH);
        float bin_w = rw * (1.0f / OUTW);
        float ty = (i + 0.5f) * (1.0f / SRR);
        float tx = (j + 0.5f) * (1.0f / SRR);
        float yy = -rh * 0.5f + ty * bin_h;
        float xx = -rw * 0.5f + tx * bin_w;
        float y = yy * ct - xx * st + ch;
        float x = yy * st + xx * ct + cw;

        bool empty = (y < -1.0f) | (y > (float)HH) | (x < -1.0f) | (x > (float)WW);
        y = fmaxf(y, 0.0f);
        x = fmaxf(x, 0.0f);
        int yl = min((int)floorf(y), HH - 1);
        int xl = min((int)floorf(x), WW - 1);
        int yh = min(yl + 1, HH - 1);
        int xh = min(xl + 1, WW - 1);
        float ly = fminf(y - (float)yl, 1.0f);
        float lx = fminf(x - (float)xl, 1.0f);
        float hy = 1.0f - ly, hx = 1.0f - lx;
        float w1 = hy * hx, w2 = hy * lx, w3 = ly * hx, w4 = ly * lx;
        if (empty) { w1 = w2 = w3 = w4 = 0.0f; }

        // offsets in half2 units: pixel * CC/2 = pixel * 128
        sm.o[s] = make_int4((yl * WW + xl) * (CC / 2), (yl * WW + xh) * (CC / 2),
                            (yh * WW + xl) * (CC / 2), (yh * WW + xh) * (CC / 2));
        sm.w[s] = make_float4(w1, w2, w3, w4);
    }
    if (tid == 0) sm.base_b = (int)r[0];
    __syncthreads();

    // thread owns channels {2*tid, 2*tid+1}
    const __half2* __restrict__ f =
        (const __half2*)(g_nhwcH + (size_t)sm.base_b * HWC) + tid;
    float* __restrict__ o_roi = out + (size_t)n * (CC * NBINS);
    float* __restrict__ stagef = (float*)sm.stage;

    const int b_lo = (blockIdx.y == 0) ? 0 : 28;
    const int b_hi = (blockIdx.y == 0) ? 28 : 49;

    for (int b0 = b_lo; b0 < b_hi; b0 += CHB) {
#pragma unroll 1
        for (int bi = 0; bi < CHB; bi++) {
            int bin = b0 + bi;
            int ph = bin / OUTW, pw = bin % OUTW;
            float ax = 0.0f, ay = 0.0f;
#pragma unroll
            for (int iy = 0; iy < SRR; iy++) {
#pragma unroll
                for (int ix = 0; ix < SRR; ix++) {
                    int s = (ph * SRR + iy) * (OUTW * SRR) + (pw * SRR + ix);
                    int4   o = sm.o[s];
                    float4 w = sm.w[s];
                    float2 v1 = __half22float2(__ldg(f + o.x));
                    float2 v2 = __half22float2(__ldg(f + o.y));
                    float2 v3 = __half22float2(__ldg(f + o.z));
                    float2 v4 = __half22float2(__ldg(f + o.w));
                    ax += w.x * v1.x; ay += w.x * v1.y;
                    ax += w.y * v2.x; ay += w.y * v2.y;
                    ax += w.z * v3.x; ay += w.z * v3.y;
                    ax += w.w * v4.x; ay += w.w * v4.y;
                }
            }
            sm.stage[bi * (SPADF / 2) + tid] = make_float2(ax * 0.25f, ay * 0.25f);
        }
        __syncthreads();
        for (int k = tid; k < CC * CHB; k += TPB) {
            int c   = k / CHB;
            int bin = k % CHB;
            o_roi[c * NBINS + b0 + bin] = stagef[bin * SPADF + c];
        }
        __syncthreads();
    }
}

// ---------------------------------------------------------------------------
extern "C" void kernel_launch(void* const* d_in, const int* in_sizes, int n_in,
                              void* d_out, int out_size) {
    const float* feats = (const float*)d_in[0];  // (2,256,200,304) f32
    const float* rois  = (const float*)d_in[1];  // (N,6) f32
    float* out = (float*)d_out;                  // (N,256,7,7) f32
    int n_rois = in_sizes[1] / 6;

    dim3 tgrid((HW + 31) / 32, CC / 64, BB);
    nchw_to_nhwc_h<<<tgrid, dim3(32, 8)>>>(feats);

    roi_align_rotated<<<dim3(n_rois, 2), TPB>>>(rois, out);
}

// round 4
// speedup vs baseline: 1.9085x; 1.1692x over previous
#include <cuda_runtime.h>
#include <cuda_fp16.h>
#include <math.h>

#define BB 2
#define CC 256
#define HH 200
#define WW 304
#define HW (HH * WW)
#define HWC (HH * WW * CC)
#define OUTH 7
#define OUTW 7
#define NBINS (OUTH * OUTW)
#define SRR 2
#define NSAMP (OUTH * SRR * OUTW * SRR)   /* 196 */
#define SCALE 0.25f

// NHWC fp16 scratch as uint2 so 8-byte gathers are guaranteed aligned.
// (B, H, W, C) halves = BB*HW*CC/4 uint2 = 62.3 MB (L2-resident).
__device__ uint2 g_nhwc2[(size_t)BB * HW * (CC / 4)];

// ---------------------------------------------------------------------------
// Kernel 1: NCHW f32 -> NHWC fp16. Tile 64 channels x 32 hw positions.
// ---------------------------------------------------------------------------
__global__ __launch_bounds__(256) void nchw_to_nhwc_h(const float* __restrict__ in) {
    __shared__ float tile[64][33];
    const int b   = blockIdx.z;
    const int hw0 = blockIdx.x * 32;
    const int c0  = blockIdx.y * 64;
    const int tx  = threadIdx.x;       // 0..31
    const int ty  = threadIdx.y;       // 0..7

    const float* src = in + (size_t)b * CC * HW;
#pragma unroll
    for (int i = 0; i < 64; i += 8) {
        int c  = c0 + ty + i;
        int hw = hw0 + tx;
        float v = 0.0f;
        if (hw < HW) v = src[(size_t)c * HW + hw];
        tile[ty + i][tx] = v;
    }
    __syncthreads();

    __half2* dst = (__half2*)g_nhwc2 + (size_t)b * HW * (CC / 2);
#pragma unroll
    for (int i = 0; i < 32; i += 8) {
        int hw = hw0 + ty + i;
        if (hw < HW) {
            float va = tile[2 * tx][ty + i];
            float vb = tile[2 * tx + 1][ty + i];
            dst[((size_t)hw * CC + c0) / 2 + tx] = __floats2half2_rn(va, vb);
        }
    }
}

// ---------------------------------------------------------------------------
// Kernel 2: rotated ROI align on fp16 NHWC.
// Grid (n_rois, 2), block 128 = 2 subgroups of 64 threads.
// Each subgroup's 64 threads cover all 256 channels (4 ch/thread, 8B gathers).
// Bin ranges: sub-range r0 = 14*(2*by+sub): [0,14) [14,28) [28,42) [42,49).
// Every 7-bin chunk is full (7 bins) or empty -> uniform barriers, constant
// divisors. fp32 accumulation, fp16 stage (7.3 KB), coalesced f32 flush.
// ---------------------------------------------------------------------------
#define TPB 128

struct AlignSmem {
    int4   o[NSAMP];             // 4 corner offsets in uint2 units (pix*64)
    float4 w[NSAMP];             // 4 bilinear weights (zeroed if empty)
    __half stage[2][7][260];     // [subgroup][bin-in-chunk][channel]
    int    base_b;
};

__global__ __launch_bounds__(TPB, 10) void roi_align_rotated(
    const float* __restrict__ rois, float* __restrict__ out) {
    __shared__ AlignSmem sm;
    const int n   = blockIdx.x;
    const int tid = threadIdx.x;
    const int sub = tid >> 6;        // 0/1: bin subgroup
    const int lt  = tid & 63;        // channel-group lane
    const float* r = rois + (size_t)n * 6;

#pragma unroll
    for (int s = tid; s < NSAMP; s += TPB) {
        float cw = r[1] * SCALE - 0.5f;
        float ch = r[2] * SCALE - 0.5f;
        float rw = r[3] * SCALE;
        float rh = r[4] * SCALE;
        float theta = r[5] * (float)(M_PI / 180.0);
        float st, ct;
        sincosf(theta, &st, &ct);

        int i = s / (OUTW * SRR);   // y sample index 0..13
        int j = s % (OUTW * SRR);   // x sample index 0..13
        float bin_h = rh * (1.0f / OUTH);
        float bin_w = rw * (1.0f / OUTW);
        float ty = (i + 0.5f) * (1.0f / SRR);
        float tx = (j + 0.5f) * (1.0f / SRR);
        float yy = -rh * 0.5f + ty * bin_h;
        float xx = -rw * 0.5f + tx * bin_w;
        float y = yy * ct - xx * st + ch;
        float x = yy * st + xx * ct + cw;

        bool empty = (y < -1.0f) | (y > (float)HH) | (x < -1.0f) | (x > (float)WW);
        y = fmaxf(y, 0.0f);
        x = fmaxf(x, 0.0f);
        int yl = min((int)floorf(y), HH - 1);
        int xl = min((int)floorf(x), WW - 1);
        int yh = min(yl + 1, HH - 1);
        int xh = min(xl + 1, WW - 1);
        float ly = fminf(y - (float)yl, 1.0f);
        float lx = fminf(x - (float)xl, 1.0f);
        float hy = 1.0f - ly, hx = 1.0f - lx;
        float w1 = hy * hx, w2 = hy * lx, w3 = ly * hx, w4 = ly * lx;
        if (empty) { w1 = w2 = w3 = w4 = 0.0f; }

        // offsets in uint2 (=4 half) units: pixel * CC/4 = pixel * 64
        sm.o[s] = make_int4((yl * WW + xl) * (CC / 4), (yl * WW + xh) * (CC / 4),
                            (yh * WW + xl) * (CC / 4), (yh * WW + xh) * (CC / 4));
        sm.w[s] = make_float4(w1, w2, w3, w4);
    }
    if (tid == 0) sm.base_b = (int)r[0];
    __syncthreads();

    // thread owns channels {4lt .. 4lt+3}
    const uint2* __restrict__ f =
        g_nhwc2 + (size_t)sm.base_b * (HW * (CC / 4)) + lt;
    float* __restrict__ o_roi = out + (size_t)n * (CC * NBINS);

    const int r0 = 14 * (2 * blockIdx.y + sub);   // 0 / 14 / 28 / 42
    const int r1 = min(r0 + 14, NBINS);

#pragma unroll 1
    for (int ck = 0; ck < 2; ck++) {
        const int b0 = r0 + 7 * ck;
        const int full = (b0 + 7 <= r1);          // chunk is 7 bins or 0
        if (full) {
#pragma unroll 1
            for (int bi = 0; bi < 7; bi++) {
                int bin = b0 + bi;
                int ph = bin / OUTW, pw = bin % OUTW;
                float a0 = 0.f, a1 = 0.f, a2 = 0.f, a3 = 0.f;
#pragma unroll
                for (int iy = 0; iy < SRR; iy++) {
#pragma unroll
                    for (int ix = 0; ix < SRR; ix++) {
                        int s = (ph * SRR + iy) * (OUTW * SRR) + (pw * SRR + ix);
                        int4   o = sm.o[s];
                        float4 w = sm.w[s];
                        uint2 p1 = __ldg(f + o.x);
                        uint2 p2 = __ldg(f + o.y);
                        uint2 p3 = __ldg(f + o.z);
                        uint2 p4 = __ldg(f + o.w);
                        float2 va, vb;
                        va = __half22float2(*(__half2*)&p1.x);
                        vb = __half22float2(*(__half2*)&p1.y);
                        a0 += w.x * va.x; a1 += w.x * va.y;
                        a2 += w.x * vb.x; a3 += w.x * vb.y;
                        va = __half22float2(*(__half2*)&p2.x);
                        vb = __half22float2(*(__half2*)&p2.y);
                        a0 += w.y * va.x; a1 += w.y * va.y;
                        a2 += w.y * vb.x; a3 += w.y * vb.y;
                        va = __half22float2(*(__half2*)&p3.x);
                        vb = __half22float2(*(__half2*)&p3.y);
                        a0 += w.z * va.x; a1 += w.z * va.y;
                        a2 += w.z * vb.x; a3 += w.z * vb.y;
                        va = __half22float2(*(__half2*)&p4.x);
                        vb = __half22float2(*(__half2*)&p4.y);
                        a0 += w.w * va.x; a1 += w.w * va.y;
                        a2 += w.w * vb.x; a3 += w.w * vb.y;
                    }
                }
                // pack 4 results as 4 halves -> one 8B smem store
                __half2 h01 = __floats2half2_rn(a0 * 0.25f, a1 * 0.25f);
                __half2 h23 = __floats2half2_rn(a2 * 0.25f, a3 * 0.25f);
                uint2 pk;
                pk.x = *(unsigned*)&h01;
                pk.y = *(unsigned*)&h23;
                *((uint2*)&sm.stage[sub][bi][0] + lt) = pk;
            }
        }
        __syncthreads();
        if (full) {
            // coalesced flush: consecutive k -> runs of 7 consecutive floats
            for (int k = lt; k < CC * 7; k += 64) {
                int c  = k / 7;
                int bb = k - c * 7;
                o_roi[c * NBINS + b0 + bb] = __half2float(sm.stage[sub][bb][c]);
            }
        }
        __syncthreads();
    }
}

// ---------------------------------------------------------------------------
extern "C" void kernel_launch(void* const* d_in, const int* in_sizes, int n_in,
                              void* d_out, int out_size) {
    const float* feats = (const float*)d_in[0];  // (2,256,200,304) f32
    const float* rois  = (const float*)d_in[1];  // (N,6) f32
    float* out = (float*)d_out;                  // (N,256,7,7) f32
    int n_rois = in_sizes[1] / 6;

    dim3 tgrid((HW + 31) / 32, CC / 64, BB);
    nchw_to_nhwc_h<<<tgrid, dim3(32, 8)>>>(feats);

    roi_align_rotated<<<dim3(n_rois, 2), TPB>>>(rois, out);
}